// round 16
// baseline (speedup 1.0000x reference)
#include <cuda_runtime.h>
#include <cuda_bf16.h>
#include <cstdint>

#define TT 2048
#define DD 1024
#define HH 16
#define DHH 64

// ---------------- scratch (no allocations allowed) ----------------
__device__ float g_Q[HH * TT * DHH];     // (H, T, DH)
__device__ float g_K[HH * TT * DHH];
__device__ float g_V[HH * TT * DHH];
__device__ float g_OH[TT * DD];          // merged (T, D)
__device__ float g_attn_scratch[(size_t)HH * TT * TT];

// ---------------- bf16 hi/lo split helpers ----------------
__device__ __forceinline__ void split2(float x0, float x1, unsigned& hi, unsigned& lo) {
    __nv_bfloat16 h0 = __float2bfloat16(x0);
    __nv_bfloat16 h1 = __float2bfloat16(x1);
    float r0 = x0 - __bfloat162float(h0);
    float r1 = x1 - __bfloat162float(h1);
    __nv_bfloat16 l0 = __float2bfloat16(r0);
    __nv_bfloat16 l1 = __float2bfloat16(r1);
    hi = (unsigned)__bfloat16_as_ushort(h0) | ((unsigned)__bfloat16_as_ushort(h1) << 16);
    lo = (unsigned)__bfloat16_as_ushort(l0) | ((unsigned)__bfloat16_as_ushort(l1) << 16);
}

__device__ __forceinline__ void split1(float x, unsigned short& h, unsigned short& l) {
    __nv_bfloat16 hb = __float2bfloat16(x);
    float r = x - __bfloat162float(hb);
    __nv_bfloat16 lb = __float2bfloat16(r);
    h = __bfloat16_as_ushort(hb);
    l = __bfloat16_as_ushort(lb);
}

// mma.sync m16n8k16 bf16: D += A*B  (PROVEN R8/R9)
__device__ __forceinline__ void mma16(float* c, const unsigned* a, const unsigned* b) {
    asm volatile(
        "mma.sync.aligned.m16n8k16.row.col.f32.bf16.bf16.f32 "
        "{%0,%1,%2,%3}, {%4,%5,%6,%7}, {%8,%9}, {%0,%1,%2,%3};"
        : "+f"(c[0]), "+f"(c[1]), "+f"(c[2]), "+f"(c[3])
        : "r"(a[0]), "r"(a[1]), "r"(a[2]), "r"(a[3]), "r"(b[0]), "r"(b[1]));
}

// =================================================================
// GEMM (bf16 split, WIDE BN=128): out = X @ W^T
// MODE 0: qkv; MODE 1: proj (X = g_OH via device symbol)
// BM=128, BN=128, BK=32, 256 threads, 8 warps (warp tile 32x64)
// (fragment pattern identical to the proven scores kernel)
// =================================================================
template<int MODE>
__global__ __launch_bounds__(256)
void gemm_kernel(const float* __restrict__ Xin,
                 const float* __restrict__ W0,
                 const float* __restrict__ W1,
                 const float* __restrict__ W2,
                 float* __restrict__ out_direct) {
    const float* X;
    const float* W;
    float* outp;
    if (MODE == 0) {
        X    = Xin;
        W    = (blockIdx.z == 0) ? W0 : (blockIdx.z == 1) ? W1 : W2;
        outp = (blockIdx.z == 0) ? g_Q : (blockIdx.z == 1) ? g_K : g_V;
    } else {
        X = g_OH;            // device-side symbol (NOT a host-passed pointer)
        W = W0;
        outp = out_direct;
    }

    __shared__ unsigned AsH[128][18], AsL[128][18];
    __shared__ unsigned BsH[128][18], BsL[128][18];

    const int tid  = threadIdx.x;
    const int warp = tid >> 5, lane = tid & 31;
    const int g = lane >> 2, t4 = lane & 3;
    const int wm = (warp >> 1) * 32, wn = (warp & 1) * 64;
    const int m0 = blockIdx.y * 128, n0 = blockIdx.x * 128;

    const int lr  = tid >> 3;
    const int fc  = (tid & 7) * 4;
    const int wix = (tid & 7) * 2;

    float C[2][8][4] = {};

    for (int k0 = 0; k0 < DD; k0 += 32) {
        #pragma unroll
        for (int p = 0; p < 4; p++) {
            int row = p * 32 + lr;
            float4 v = *(const float4*)&X[(size_t)(m0 + row) * DD + k0 + fc];
            unsigned h0, l0, h1, l1;
            split2(v.x, v.y, h0, l0);
            split2(v.z, v.w, h1, l1);
            AsH[row][wix] = h0; AsH[row][wix + 1] = h1;
            AsL[row][wix] = l0; AsL[row][wix + 1] = l1;
            float4 w = *(const float4*)&W[(size_t)(n0 + row) * DD + k0 + fc];
            split2(w.x, w.y, h0, l0);
            split2(w.z, w.w, h1, l1);
            BsH[row][wix] = h0; BsH[row][wix + 1] = h1;
            BsL[row][wix] = l0; BsL[row][wix + 1] = l1;
        }
        __syncthreads();

        #pragma unroll
        for (int ks = 0; ks < 2; ks++) {
            const int kb = ks * 8;
            unsigned aH[2][4], aL[2][4];
            #pragma unroll
            for (int mt = 0; mt < 2; mt++) {
                int r = wm + mt * 16 + g;
                aH[mt][0] = AsH[r][kb + t4];     aH[mt][1] = AsH[r + 8][kb + t4];
                aH[mt][2] = AsH[r][kb + t4 + 4]; aH[mt][3] = AsH[r + 8][kb + t4 + 4];
                aL[mt][0] = AsL[r][kb + t4];     aL[mt][1] = AsL[r + 8][kb + t4];
                aL[mt][2] = AsL[r][kb + t4 + 4]; aL[mt][3] = AsL[r + 8][kb + t4 + 4];
            }
            #pragma unroll
            for (int nt = 0; nt < 8; nt++) {
                int c = wn + nt * 8 + g;
                unsigned bH[2], bL[2];
                bH[0] = BsH[c][kb + t4]; bH[1] = BsH[c][kb + t4 + 4];
                bL[0] = BsL[c][kb + t4]; bL[1] = BsL[c][kb + t4 + 4];
                #pragma unroll
                for (int mt = 0; mt < 2; mt++) {
                    mma16(C[mt][nt], aH[mt], bH);
                    mma16(C[mt][nt], aH[mt], bL);
                    mma16(C[mt][nt], aL[mt], bH);
                }
            }
        }
        __syncthreads();
    }

    #pragma unroll
    for (int mt = 0; mt < 2; mt++) {
        #pragma unroll
        for (int nt = 0; nt < 8; nt++) {
            #pragma unroll
            for (int half = 0; half < 2; half++) {
                int r0 = m0 + wm + mt * 16 + g + half * 8;
                int cc = n0 + wn + nt * 8 + 2 * t4;
                float2 v = make_float2(C[mt][nt][half * 2], C[mt][nt][half * 2 + 1]);
                if (MODE == 0) {
                    int head = cc >> 6, cd = cc & 63;
                    *(float2*)&outp[(size_t)head * TT * DHH + (size_t)r0 * DHH + cd] = v;
                } else {
                    *(float2*)&outp[(size_t)r0 * DD + cc] = v;
                }
            }
        }
    }
}

// =================================================================
// Scores (PROVEN R15 single-phase): raw S = Q K^T / 8, causal.
// Full DH=64 staged at once, ONE barrier. 128x128 tile, 256 threads.
// Dynamic smem: 4 * 128*36*4 = 73728 B.
// =================================================================
__global__ __launch_bounds__(256)
void scores_kernel(float* __restrict__ attn) {
    const int h = blockIdx.z, qt = blockIdx.y, kt = blockIdx.x;
    const int q0 = qt * 128, k0c = kt * 128;
    float* dst = attn + (size_t)h * TT * TT;
    const int tid = threadIdx.x;

    if (kt > qt) {  // fully masked tile -> 0 (d_out poisoned, must write)
        const float4 z = make_float4(0.f, 0.f, 0.f, 0.f);
        for (int idx = tid; idx < 128 * 32; idx += 256) {
            int r = idx >> 5, c = (idx & 31) * 4;
            *(float4*)&dst[(size_t)(q0 + r) * TT + k0c + c] = z;
        }
        return;
    }

    extern __shared__ char dsm[];
    unsigned (*QsH)[36] = (unsigned (*)[36])(dsm);
    unsigned (*QsL)[36] = (unsigned (*)[36])(dsm + 18432);
    unsigned (*KsH)[36] = (unsigned (*)[36])(dsm + 36864);
    unsigned (*KsL)[36] = (unsigned (*)[36])(dsm + 55296);

    const int warp = tid >> 5, lane = tid & 31;
    const int g = lane >> 2, t4 = lane & 3;
    const int wm = (warp >> 1) * 32, wn = (warp & 1) * 64;

    const int lr  = tid >> 3;
    const int fc  = (tid & 7) * 4;
    const int wix = (tid & 7) * 2;

    #pragma unroll
    for (int p = 0; p < 4; p++) {
        int row = p * 32 + lr;
        #pragma unroll
        for (int s = 0; s < 2; s++) {
            int w2 = s * 16 + wix;
            float4 v = *(const float4*)&g_Q[((size_t)h * TT + q0 + row) * DHH + s * 32 + fc];
            unsigned h0, l0, h1, l1;
            split2(v.x, v.y, h0, l0); split2(v.z, v.w, h1, l1);
            QsH[row][w2] = h0; QsH[row][w2 + 1] = h1;
            QsL[row][w2] = l0; QsL[row][w2 + 1] = l1;
            float4 w = *(const float4*)&g_K[((size_t)h * TT + k0c + row) * DHH + s * 32 + fc];
            split2(w.x, w.y, h0, l0); split2(w.z, w.w, h1, l1);
            KsH[row][w2] = h0; KsH[row][w2 + 1] = h1;
            KsL[row][w2] = l0; KsL[row][w2 + 1] = l1;
        }
    }
    __syncthreads();

    float C[2][8][4] = {};

    #pragma unroll
    for (int ks = 0; ks < 4; ks++) {
        const int kb = ks * 8;
        unsigned aH[2][4], aL[2][4];
        #pragma unroll
        for (int mt = 0; mt < 2; mt++) {
            int r = wm + mt * 16 + g;
            aH[mt][0] = QsH[r][kb + t4];     aH[mt][1] = QsH[r + 8][kb + t4];
            aH[mt][2] = QsH[r][kb + t4 + 4]; aH[mt][3] = QsH[r + 8][kb + t4 + 4];
            aL[mt][0] = QsL[r][kb + t4];     aL[mt][1] = QsL[r + 8][kb + t4];
            aL[mt][2] = QsL[r][kb + t4 + 4]; aL[mt][3] = QsL[r + 8][kb + t4 + 4];
        }
        #pragma unroll
        for (int nt = 0; nt < 8; nt++) {
            int c = wn + nt * 8 + g;
            unsigned bH[2], bL[2];
            bH[0] = KsH[c][kb + t4]; bH[1] = KsH[c][kb + t4 + 4];
            bL[0] = KsL[c][kb + t4]; bL[1] = KsL[c][kb + t4 + 4];
            #pragma unroll
            for (int mt = 0; mt < 2; mt++) {
                mma16(C[mt][nt], aH[mt], bH);
                mma16(C[mt][nt], aH[mt], bL);
                mma16(C[mt][nt], aL[mt], bH);
            }
        }
    }

    const bool diag = (kt == qt);
    const float scale = 0.125f;  // 1/sqrt(64)
    #pragma unroll
    for (int mt = 0; mt < 2; mt++) {
        #pragma unroll
        for (int nt = 0; nt < 8; nt++) {
            #pragma unroll
            for (int half = 0; half < 2; half++) {
                int r = q0 + wm + mt * 16 + g + half * 8;
                float e0 = C[mt][nt][half * 2] * scale;
                float e1 = C[mt][nt][half * 2 + 1] * scale;
                int c0 = k0c + wn + nt * 8 + 2 * t4;
                if (diag) {
                    if (c0 > r) e0 = 0.f;
                    if (c0 + 1 > r) e1 = 0.f;
                }
                *(float2*)&dst[(size_t)r * TT + c0] = make_float2(e0, e1);
            }
        }
    }
}

// =================================================================
// Softmax (PROVEN R14 no-max): p = exp(s)/sum over prefix [0, q].
// =================================================================
__global__ __launch_bounds__(256)
void softmax_kernel(float* __restrict__ attn) {
    const int q = blockIdx.x, h = blockIdx.y;
    float* row = attn + (size_t)h * TT * TT + (size_t)q * TT;
    const int n = q + 1;
    const int tid = threadIdx.x;

    float vals[8];
    int cnt = 0;
    for (int c = tid; c < n; c += 256) vals[cnt++] = row[c];

    __shared__ float red[32];

    float s = 0.f;
    for (int i = 0; i < cnt; i++) { vals[i] = __expf(vals[i]); s += vals[i]; }
    #pragma unroll
    for (int o = 16; o; o >>= 1) s += __shfl_xor_sync(0xffffffffu, s, o);
    if ((tid & 31) == 0) red[tid >> 5] = s;
    __syncthreads();
    if (tid < 32) {
        float v = (tid < 8) ? red[tid] : 0.f;
        #pragma unroll
        for (int o = 4; o; o >>= 1) v += __shfl_xor_sync(0xffffffffu, v, o);
        if (tid == 0) red[0] = v;
    }
    __syncthreads();
    const float inv = 1.f / red[0];

    cnt = 0;
    for (int c = tid; c < n; c += 256) row[c] = vals[cnt++] * inv;
}

// =================================================================
// AV (PROVEN R12: single-buffer + register prefetch): OH = attn_h @ V_h.
// 128x64 tile, 256 threads, 8 warps (warp tile 32x32), BK=32 causal loop.
// =================================================================
__global__ __launch_bounds__(256)
void av_kernel(const float* __restrict__ attn) {
    const int h = blockIdx.y;
    const int qt = (int)gridDim.x - 1 - (int)blockIdx.x;   // descending size
    const int q0 = qt * 128;
    const float* A = attn + (size_t)h * TT * TT;
    const float* V = g_V + (size_t)h * TT * DHH;
    const int tid = threadIdx.x;

    __shared__ unsigned PsH[128][18], PsL[128][18];          // [q][kword]
    __shared__ unsigned short VTH[64][36], VTL[64][36];      // [n][k] transposed

    const int warp = tid >> 5, lane = tid & 31;
    const int g = lane >> 2, t4 = lane & 3;
    const int wm = (warp >> 1) * 32, wn = (warp & 1) * 32;

    const int lr  = tid >> 3;
    const int fc  = (tid & 7) * 4;
    const int wix = (tid & 7) * 2;
    const int vrow = tid >> 3, vcol = (tid & 7) * 8;

    float C[2][4][4] = {};
    const int kend = q0 + 128;   // attn==0 beyond q: exact

    // ---- prefetch registers ----
    float4 pA[4];
    float4 pV0, pV1;

    #pragma unroll
    for (int p = 0; p < 4; p++)
        pA[p] = *(const float4*)&A[(size_t)(q0 + p * 32 + lr) * TT + fc];
    pV0 = *(const float4*)&V[(size_t)vrow * DHH + vcol];
    pV1 = *(const float4*)&V[(size_t)vrow * DHH + vcol + 4];

    for (int k0 = 0; k0 < kend; k0 += 32) {
        #pragma unroll
        for (int p = 0; p < 4; p++) {
            int row = p * 32 + lr;
            unsigned h0, l0, h1, l1;
            split2(pA[p].x, pA[p].y, h0, l0); split2(pA[p].z, pA[p].w, h1, l1);
            PsH[row][wix] = h0; PsH[row][wix + 1] = h1;
            PsL[row][wix] = l0; PsL[row][wix + 1] = l1;
        }
        {
            unsigned short sh, sl;
            split1(pV0.x, sh, sl); VTH[vcol + 0][vrow] = sh; VTL[vcol + 0][vrow] = sl;
            split1(pV0.y, sh, sl); VTH[vcol + 1][vrow] = sh; VTL[vcol + 1][vrow] = sl;
            split1(pV0.z, sh, sl); VTH[vcol + 2][vrow] = sh; VTL[vcol + 2][vrow] = sl;
            split1(pV0.w, sh, sl); VTH[vcol + 3][vrow] = sh; VTL[vcol + 3][vrow] = sl;
            split1(pV1.x, sh, sl); VTH[vcol + 4][vrow] = sh; VTL[vcol + 4][vrow] = sl;
            split1(pV1.y, sh, sl); VTH[vcol + 5][vrow] = sh; VTL[vcol + 5][vrow] = sl;
            split1(pV1.z, sh, sl); VTH[vcol + 6][vrow] = sh; VTL[vcol + 6][vrow] = sl;
            split1(pV1.w, sh, sl); VTH[vcol + 7][vrow] = sh; VTL[vcol + 7][vrow] = sl;
        }
        __syncthreads();

        const int kn = k0 + 32;
        if (kn < kend) {
            #pragma unroll
            for (int p = 0; p < 4; p++)
                pA[p] = *(const float4*)&A[(size_t)(q0 + p * 32 + lr) * TT + kn + fc];
            pV0 = *(const float4*)&V[(size_t)(kn + vrow) * DHH + vcol];
            pV1 = *(const float4*)&V[(size_t)(kn + vrow) * DHH + vcol + 4];
        }

        #pragma unroll
        for (int ks = 0; ks < 2; ks++) {
            const int kb  = ks * 8;
            const int ke  = ks * 16;
            unsigned aH[2][4], aL[2][4];
            #pragma unroll
            for (int mt = 0; mt < 2; mt++) {
                int r = wm + mt * 16 + g;
                aH[mt][0] = PsH[r][kb + t4];     aH[mt][1] = PsH[r + 8][kb + t4];
                aH[mt][2] = PsH[r][kb + t4 + 4]; aH[mt][3] = PsH[r + 8][kb + t4 + 4];
                aL[mt][0] = PsL[r][kb + t4];     aL[mt][1] = PsL[r + 8][kb + t4];
                aL[mt][2] = PsL[r][kb + t4 + 4]; aL[mt][3] = PsL[r + 8][kb + t4 + 4];
            }
            #pragma unroll
            for (int nt = 0; nt < 4; nt++) {
                int c = wn + nt * 8 + g;
                unsigned bH[2], bL[2];
                bH[0] = *(const unsigned*)&VTH[c][ke + 2 * t4];
                bH[1] = *(const unsigned*)&VTH[c][ke + 2 * t4 + 8];
                bL[0] = *(const unsigned*)&VTL[c][ke + 2 * t4];
                bL[1] = *(const unsigned*)&VTL[c][ke + 2 * t4 + 8];
                #pragma unroll
                for (int mt = 0; mt < 2; mt++) {
                    mma16(C[mt][nt], aH[mt], bH);
                    mma16(C[mt][nt], aH[mt], bL);
                    mma16(C[mt][nt], aL[mt], bH);
                }
            }
        }
        __syncthreads();
    }

    #pragma unroll
    for (int mt = 0; mt < 2; mt++) {
        #pragma unroll
        for (int nt = 0; nt < 4; nt++) {
            int r0 = q0 + wm + mt * 16 + g;
            int cc = h * DHH + wn + nt * 8 + 2 * t4;
            *(float2*)&g_OH[(size_t)r0 * DD + cc] =
                make_float2(C[mt][nt][0], C[mt][nt][1]);
            *(float2*)&g_OH[(size_t)(r0 + 8) * DD + cc] =
                make_float2(C[mt][nt][2], C[mt][nt][3]);
        }
    }
}

// =================================================================
extern "C" void kernel_launch(void* const* d_in, const int* in_sizes, int n_in,
                              void* d_out, int out_size) {
    (void)in_sizes; (void)n_in;
    const float* x  = (const float*)d_in[0];
    const float* Wq = (const float*)d_in[1];
    const float* Wk = (const float*)d_in[2];
    const float* Wv = (const float*)d_in[3];
    const float* Wo = (const float*)d_in[4];

    float* outp = (float*)d_out;
    const long long OUT_E  = (long long)TT * DD;
    const long long ATTN_E = (long long)HH * TT * TT;

    float* attn;
    if ((long long)out_size >= OUT_E + ATTN_E) {
        attn = outp + OUT_E;
    } else {
        void* p = 0;
        cudaGetSymbolAddress(&p, g_attn_scratch);
        attn = (float*)p;
    }

    const int SCORES_SMEM = 73728;
    cudaFuncSetAttribute(scores_kernel, cudaFuncAttributeMaxDynamicSharedMemorySize, SCORES_SMEM);

    gemm_kernel<0><<<dim3(DD / 128, TT / 128, 3), 256>>>(x, Wq, Wk, Wv, nullptr);
    scores_kernel <<<dim3(TT / 128, TT / 128, HH), 256, SCORES_SMEM>>>(attn);
    softmax_kernel<<<dim3(TT, HH), 256>>>(attn);
    av_kernel     <<<dim3(TT / 128, HH), 256>>>(attn);
    // MODE 1 reads g_OH via device-side symbol (host passes nullptr!)
    gemm_kernel<1><<<dim3(DD / 128, TT / 128, 1), 256>>>(nullptr, Wo, nullptr, nullptr, outp);
}

// round 17
// speedup vs baseline: 1.0378x; 1.0378x over previous
#include <cuda_runtime.h>
#include <cuda_bf16.h>
#include <cstdint>

#define TT 2048
#define DD 1024
#define HH 16
#define DHH 64

// ---------------- scratch (no allocations allowed) ----------------
__device__ float g_Q[HH * TT * DHH];     // (H, T, DH)
__device__ float g_K[HH * TT * DHH];
__device__ float g_V[HH * TT * DHH];
__device__ float g_OH[TT * DD];          // merged (T, D)
__device__ float g_attn_scratch[(size_t)HH * TT * TT];

// ---------------- bf16 hi/lo split helpers ----------------
__device__ __forceinline__ void split2(float x0, float x1, unsigned& hi, unsigned& lo) {
    __nv_bfloat16 h0 = __float2bfloat16(x0);
    __nv_bfloat16 h1 = __float2bfloat16(x1);
    float r0 = x0 - __bfloat162float(h0);
    float r1 = x1 - __bfloat162float(h1);
    __nv_bfloat16 l0 = __float2bfloat16(r0);
    __nv_bfloat16 l1 = __float2bfloat16(r1);
    hi = (unsigned)__bfloat16_as_ushort(h0) | ((unsigned)__bfloat16_as_ushort(h1) << 16);
    lo = (unsigned)__bfloat16_as_ushort(l0) | ((unsigned)__bfloat16_as_ushort(l1) << 16);
}

__device__ __forceinline__ void split1(float x, unsigned short& h, unsigned short& l) {
    __nv_bfloat16 hb = __float2bfloat16(x);
    float r = x - __bfloat162float(hb);
    __nv_bfloat16 lb = __float2bfloat16(r);
    h = __bfloat16_as_ushort(hb);
    l = __bfloat16_as_ushort(lb);
}

// mma.sync m16n8k16 bf16: D += A*B  (PROVEN R8/R9)
__device__ __forceinline__ void mma16(float* c, const unsigned* a, const unsigned* b) {
    asm volatile(
        "mma.sync.aligned.m16n8k16.row.col.f32.bf16.bf16.f32 "
        "{%0,%1,%2,%3}, {%4,%5,%6,%7}, {%8,%9}, {%0,%1,%2,%3};"
        : "+f"(c[0]), "+f"(c[1]), "+f"(c[2]), "+f"(c[3])
        : "r"(a[0]), "r"(a[1]), "r"(a[2]), "r"(a[3]), "r"(b[0]), "r"(b[1]));
}

// =================================================================
// GEMM (bf16 split, PROVEN R9/R14 narrow BN=64): out = X @ W^T
// MODE 0: qkv; MODE 1: proj (X = g_OH via device symbol)
// BM=128, BN=64, BK=32, 256 threads, 8 warps (warp tile 32x32)
// =================================================================
template<int MODE>
__global__ __launch_bounds__(256)
void gemm_kernel(const float* __restrict__ Xin,
                 const float* __restrict__ W0,
                 const float* __restrict__ W1,
                 const float* __restrict__ W2,
                 float* __restrict__ out_direct) {
    const float* X;
    const float* W;
    float* outp;
    if (MODE == 0) {
        X    = Xin;
        W    = (blockIdx.z == 0) ? W0 : (blockIdx.z == 1) ? W1 : W2;
        outp = (blockIdx.z == 0) ? g_Q : (blockIdx.z == 1) ? g_K : g_V;
    } else {
        X = g_OH;            // device-side symbol (NOT a host-passed pointer)
        W = W0;
        outp = out_direct;
    }

    __shared__ unsigned AsH[128][18], AsL[128][18];
    __shared__ unsigned BsH[64][18],  BsL[64][18];

    const int tid  = threadIdx.x;
    const int warp = tid >> 5, lane = tid & 31;
    const int g = lane >> 2, t4 = lane & 3;
    const int wm = (warp >> 1) * 32, wn = (warp & 1) * 32;
    const int m0 = blockIdx.y * 128, n0 = blockIdx.x * 64;

    const int lr  = tid >> 3;
    const int fc  = (tid & 7) * 4;
    const int wix = (tid & 7) * 2;

    float C[2][4][4] = {};

    for (int k0 = 0; k0 < DD; k0 += 32) {
        #pragma unroll
        for (int p = 0; p < 4; p++) {
            int row = p * 32 + lr;
            float4 v = *(const float4*)&X[(size_t)(m0 + row) * DD + k0 + fc];
            unsigned h0, l0, h1, l1;
            split2(v.x, v.y, h0, l0);
            split2(v.z, v.w, h1, l1);
            AsH[row][wix] = h0; AsH[row][wix + 1] = h1;
            AsL[row][wix] = l0; AsL[row][wix + 1] = l1;
        }
        #pragma unroll
        for (int p = 0; p < 2; p++) {
            int row = p * 32 + lr;
            float4 v = *(const float4*)&W[(size_t)(n0 + row) * DD + k0 + fc];
            unsigned h0, l0, h1, l1;
            split2(v.x, v.y, h0, l0);
            split2(v.z, v.w, h1, l1);
            BsH[row][wix] = h0; BsH[row][wix + 1] = h1;
            BsL[row][wix] = l0; BsL[row][wix + 1] = l1;
        }
        __syncthreads();

        #pragma unroll
        for (int ks = 0; ks < 2; ks++) {
            const int kb = ks * 8;
            unsigned aH[2][4], aL[2][4], bH[4][2], bL[4][2];
            #pragma unroll
            for (int mt = 0; mt < 2; mt++) {
                int r = wm + mt * 16 + g;
                aH[mt][0] = AsH[r][kb + t4];     aH[mt][1] = AsH[r + 8][kb + t4];
                aH[mt][2] = AsH[r][kb + t4 + 4]; aH[mt][3] = AsH[r + 8][kb + t4 + 4];
                aL[mt][0] = AsL[r][kb + t4];     aL[mt][1] = AsL[r + 8][kb + t4];
                aL[mt][2] = AsL[r][kb + t4 + 4]; aL[mt][3] = AsL[r + 8][kb + t4 + 4];
            }
            #pragma unroll
            for (int nt = 0; nt < 4; nt++) {
                int c = wn + nt * 8 + g;
                bH[nt][0] = BsH[c][kb + t4]; bH[nt][1] = BsH[c][kb + t4 + 4];
                bL[nt][0] = BsL[c][kb + t4]; bL[nt][1] = BsL[c][kb + t4 + 4];
            }
            #pragma unroll
            for (int mt = 0; mt < 2; mt++)
                #pragma unroll
                for (int nt = 0; nt < 4; nt++) {
                    mma16(C[mt][nt], aH[mt], bH[nt]);
                    mma16(C[mt][nt], aH[mt], bL[nt]);
                    mma16(C[mt][nt], aL[mt], bH[nt]);
                }
        }
        __syncthreads();
    }

    #pragma unroll
    for (int mt = 0; mt < 2; mt++) {
        #pragma unroll
        for (int nt = 0; nt < 4; nt++) {
            int r0 = m0 + wm + mt * 16 + g;
            int cc = n0 + wn + nt * 8 + 2 * t4;
            float2 v0 = make_float2(C[mt][nt][0], C[mt][nt][1]);
            float2 v1 = make_float2(C[mt][nt][2], C[mt][nt][3]);
            if (MODE == 0) {
                int head = cc >> 6, cd = cc & 63;
                *(float2*)&outp[(size_t)head * TT * DHH + (size_t)r0 * DHH + cd] = v0;
                *(float2*)&outp[(size_t)head * TT * DHH + (size_t)(r0 + 8) * DHH + cd] = v1;
            } else {
                *(float2*)&outp[(size_t)r0 * DD + cc] = v0;
                *(float2*)&outp[(size_t)(r0 + 8) * DD + cc] = v1;
            }
        }
    }
}

// =================================================================
// Scores (PROVEN R15 single-phase): raw S = Q K^T / 8, causal.
// Full DH=64 staged at once, ONE barrier. 128x128 tile, 256 threads.
// Dynamic smem: 4 * 128*36*4 = 73728 B.
// =================================================================
__global__ __launch_bounds__(256)
void scores_kernel(float* __restrict__ attn) {
    const int h = blockIdx.z, qt = blockIdx.y, kt = blockIdx.x;
    const int q0 = qt * 128, k0c = kt * 128;
    float* dst = attn + (size_t)h * TT * TT;
    const int tid = threadIdx.x;

    if (kt > qt) {  // fully masked tile -> 0 (d_out poisoned, must write)
        const float4 z = make_float4(0.f, 0.f, 0.f, 0.f);
        for (int idx = tid; idx < 128 * 32; idx += 256) {
            int r = idx >> 5, c = (idx & 31) * 4;
            *(float4*)&dst[(size_t)(q0 + r) * TT + k0c + c] = z;
        }
        return;
    }

    extern __shared__ char dsm[];
    unsigned (*QsH)[36] = (unsigned (*)[36])(dsm);
    unsigned (*QsL)[36] = (unsigned (*)[36])(dsm + 18432);
    unsigned (*KsH)[36] = (unsigned (*)[36])(dsm + 36864);
    unsigned (*KsL)[36] = (unsigned (*)[36])(dsm + 55296);

    const int warp = tid >> 5, lane = tid & 31;
    const int g = lane >> 2, t4 = lane & 3;
    const int wm = (warp >> 1) * 32, wn = (warp & 1) * 64;

    const int lr  = tid >> 3;
    const int fc  = (tid & 7) * 4;
    const int wix = (tid & 7) * 2;

    #pragma unroll
    for (int p = 0; p < 4; p++) {
        int row = p * 32 + lr;
        #pragma unroll
        for (int s = 0; s < 2; s++) {
            int w2 = s * 16 + wix;
            float4 v = *(const float4*)&g_Q[((size_t)h * TT + q0 + row) * DHH + s * 32 + fc];
            unsigned h0, l0, h1, l1;
            split2(v.x, v.y, h0, l0); split2(v.z, v.w, h1, l1);
            QsH[row][w2] = h0; QsH[row][w2 + 1] = h1;
            QsL[row][w2] = l0; QsL[row][w2 + 1] = l1;
            float4 w = *(const float4*)&g_K[((size_t)h * TT + k0c + row) * DHH + s * 32 + fc];
            split2(w.x, w.y, h0, l0); split2(w.z, w.w, h1, l1);
            KsH[row][w2] = h0; KsH[row][w2 + 1] = h1;
            KsL[row][w2] = l0; KsL[row][w2 + 1] = l1;
        }
    }
    __syncthreads();

    float C[2][8][4] = {};

    #pragma unroll
    for (int ks = 0; ks < 4; ks++) {
        const int kb = ks * 8;
        unsigned aH[2][4], aL[2][4];
        #pragma unroll
        for (int mt = 0; mt < 2; mt++) {
            int r = wm + mt * 16 + g;
            aH[mt][0] = QsH[r][kb + t4];     aH[mt][1] = QsH[r + 8][kb + t4];
            aH[mt][2] = QsH[r][kb + t4 + 4]; aH[mt][3] = QsH[r + 8][kb + t4 + 4];
            aL[mt][0] = QsL[r][kb + t4];     aL[mt][1] = QsL[r + 8][kb + t4];
            aL[mt][2] = QsL[r][kb + t4 + 4]; aL[mt][3] = QsL[r + 8][kb + t4 + 4];
        }
        #pragma unroll
        for (int nt = 0; nt < 8; nt++) {
            int c = wn + nt * 8 + g;
            unsigned bH[2], bL[2];
            bH[0] = KsH[c][kb + t4]; bH[1] = KsH[c][kb + t4 + 4];
            bL[0] = KsL[c][kb + t4]; bL[1] = KsL[c][kb + t4 + 4];
            #pragma unroll
            for (int mt = 0; mt < 2; mt++) {
                mma16(C[mt][nt], aH[mt], bH);
                mma16(C[mt][nt], aH[mt], bL);
                mma16(C[mt][nt], aL[mt], bH);
            }
        }
    }

    const bool diag = (kt == qt);
    const float scale = 0.125f;  // 1/sqrt(64)
    #pragma unroll
    for (int mt = 0; mt < 2; mt++) {
        #pragma unroll
        for (int nt = 0; nt < 8; nt++) {
            #pragma unroll
            for (int half = 0; half < 2; half++) {
                int r = q0 + wm + mt * 16 + g + half * 8;
                float e0 = C[mt][nt][half * 2] * scale;
                float e1 = C[mt][nt][half * 2 + 1] * scale;
                int c0 = k0c + wn + nt * 8 + 2 * t4;
                if (diag) {
                    if (c0 > r) e0 = 0.f;
                    if (c0 + 1 > r) e1 = 0.f;
                }
                *(float2*)&dst[(size_t)r * TT + c0] = make_float2(e0, e1);
            }
        }
    }
}

// =================================================================
// Softmax (PROVEN R14 no-max): p = exp(s)/sum over prefix [0, q].
// =================================================================
__global__ __launch_bounds__(256)
void softmax_kernel(float* __restrict__ attn) {
    const int q = blockIdx.x, h = blockIdx.y;
    float* row = attn + (size_t)h * TT * TT + (size_t)q * TT;
    const int n = q + 1;
    const int tid = threadIdx.x;

    float vals[8];
    int cnt = 0;
    for (int c = tid; c < n; c += 256) vals[cnt++] = row[c];

    __shared__ float red[32];

    float s = 0.f;
    for (int i = 0; i < cnt; i++) { vals[i] = __expf(vals[i]); s += vals[i]; }
    #pragma unroll
    for (int o = 16; o; o >>= 1) s += __shfl_xor_sync(0xffffffffu, s, o);
    if ((tid & 31) == 0) red[tid >> 5] = s;
    __syncthreads();
    if (tid < 32) {
        float v = (tid < 8) ? red[tid] : 0.f;
        #pragma unroll
        for (int o = 4; o; o >>= 1) v += __shfl_xor_sync(0xffffffffu, v, o);
        if (tid == 0) red[0] = v;
    }
    __syncthreads();
    const float inv = 1.f / red[0];

    cnt = 0;
    for (int c = tid; c < n; c += 256) row[c] = vals[cnt++] * inv;
}

// =================================================================
// AV (PROVEN R12: single-buffer + register prefetch): OH = attn_h @ V_h.
// 128x64 tile, 256 threads, 8 warps (warp tile 32x32), BK=32 causal loop.
// =================================================================
__global__ __launch_bounds__(256)
void av_kernel(const float* __restrict__ attn) {
    const int h = blockIdx.y;
    const int qt = (int)gridDim.x - 1 - (int)blockIdx.x;   // descending size
    const int q0 = qt * 128;
    const float* A = attn + (size_t)h * TT * TT;
    const float* V = g_V + (size_t)h * TT * DHH;
    const int tid = threadIdx.x;

    __shared__ unsigned PsH[128][18], PsL[128][18];          // [q][kword]
    __shared__ unsigned short VTH[64][36], VTL[64][36];      // [n][k] transposed

    const int warp = tid >> 5, lane = tid & 31;
    const int g = lane >> 2, t4 = lane & 3;
    const int wm = (warp >> 1) * 32, wn = (warp & 1) * 32;

    const int lr  = tid >> 3;
    const int fc  = (tid & 7) * 4;
    const int wix = (tid & 7) * 2;
    const int vrow = tid >> 3, vcol = (tid & 7) * 8;

    float C[2][4][4] = {};
    const int kend = q0 + 128;   // attn==0 beyond q: exact

    // ---- prefetch registers ----
    float4 pA[4];
    float4 pV0, pV1;

    #pragma unroll
    for (int p = 0; p < 4; p++)
        pA[p] = *(const float4*)&A[(size_t)(q0 + p * 32 + lr) * TT + fc];
    pV0 = *(const float4*)&V[(size_t)vrow * DHH + vcol];
    pV1 = *(const float4*)&V[(size_t)vrow * DHH + vcol + 4];

    for (int k0 = 0; k0 < kend; k0 += 32) {
        #pragma unroll
        for (int p = 0; p < 4; p++) {
            int row = p * 32 + lr;
            unsigned h0, l0, h1, l1;
            split2(pA[p].x, pA[p].y, h0, l0); split2(pA[p].z, pA[p].w, h1, l1);
            PsH[row][wix] = h0; PsH[row][wix + 1] = h1;
            PsL[row][wix] = l0; PsL[row][wix + 1] = l1;
        }
        {
            unsigned short sh, sl;
            split1(pV0.x, sh, sl); VTH[vcol + 0][vrow] = sh; VTL[vcol + 0][vrow] = sl;
            split1(pV0.y, sh, sl); VTH[vcol + 1][vrow] = sh; VTL[vcol + 1][vrow] = sl;
            split1(pV0.z, sh, sl); VTH[vcol + 2][vrow] = sh; VTL[vcol + 2][vrow] = sl;
            split1(pV0.w, sh, sl); VTH[vcol + 3][vrow] = sh; VTL[vcol + 3][vrow] = sl;
            split1(pV1.x, sh, sl); VTH[vcol + 4][vrow] = sh; VTL[vcol + 4][vrow] = sl;
            split1(pV1.y, sh, sl); VTH[vcol + 5][vrow] = sh; VTL[vcol + 5][vrow] = sl;
            split1(pV1.z, sh, sl); VTH[vcol + 6][vrow] = sh; VTL[vcol + 6][vrow] = sl;
            split1(pV1.w, sh, sl); VTH[vcol + 7][vrow] = sh; VTL[vcol + 7][vrow] = sl;
        }
        __syncthreads();

        const int kn = k0 + 32;
        if (kn < kend) {
            #pragma unroll
            for (int p = 0; p < 4; p++)
                pA[p] = *(const float4*)&A[(size_t)(q0 + p * 32 + lr) * TT + kn + fc];
            pV0 = *(const float4*)&V[(size_t)(kn + vrow) * DHH + vcol];
            pV1 = *(const float4*)&V[(size_t)(kn + vrow) * DHH + vcol + 4];
        }

        #pragma unroll
        for (int ks = 0; ks < 2; ks++) {
            const int kb  = ks * 8;
            const int ke  = ks * 16;
            unsigned aH[2][4], aL[2][4];
            #pragma unroll
            for (int mt = 0; mt < 2; mt++) {
                int r = wm + mt * 16 + g;
                aH[mt][0] = PsH[r][kb + t4];     aH[mt][1] = PsH[r + 8][kb + t4];
                aH[mt][2] = PsH[r][kb + t4 + 4]; aH[mt][3] = PsH[r + 8][kb + t4 + 4];
                aL[mt][0] = PsL[r][kb + t4];     aL[mt][1] = PsL[r + 8][kb + t4];
                aL[mt][2] = PsL[r][kb + t4 + 4]; aL[mt][3] = PsL[r + 8][kb + t4 + 4];
            }
            #pragma unroll
            for (int nt = 0; nt < 4; nt++) {
                int c = wn + nt * 8 + g;
                unsigned bH[2], bL[2];
                bH[0] = *(const unsigned*)&VTH[c][ke + 2 * t4];
                bH[1] = *(const unsigned*)&VTH[c][ke + 2 * t4 + 8];
                bL[0] = *(const unsigned*)&VTL[c][ke + 2 * t4];
                bL[1] = *(const unsigned*)&VTL[c][ke + 2 * t4 + 8];
                #pragma unroll
                for (int mt = 0; mt < 2; mt++) {
                    mma16(C[mt][nt], aH[mt], bH);
                    mma16(C[mt][nt], aH[mt], bL);
                    mma16(C[mt][nt], aL[mt], bH);
                }
            }
        }
        __syncthreads();
    }

    #pragma unroll
    for (int mt = 0; mt < 2; mt++) {
        #pragma unroll
        for (int nt = 0; nt < 4; nt++) {
            int r0 = q0 + wm + mt * 16 + g;
            int cc = h * DHH + wn + nt * 8 + 2 * t4;
            *(float2*)&g_OH[(size_t)r0 * DD + cc] =
                make_float2(C[mt][nt][0], C[mt][nt][1]);
            *(float2*)&g_OH[(size_t)(r0 + 8) * DD + cc] =
                make_float2(C[mt][nt][2], C[mt][nt][3]);
        }
    }
}

// =================================================================
extern "C" void kernel_launch(void* const* d_in, const int* in_sizes, int n_in,
                              void* d_out, int out_size) {
    (void)in_sizes; (void)n_in;
    const float* x  = (const float*)d_in[0];
    const float* Wq = (const float*)d_in[1];
    const float* Wk = (const float*)d_in[2];
    const float* Wv = (const float*)d_in[3];
    const float* Wo = (const float*)d_in[4];

    float* outp = (float*)d_out;
    const long long OUT_E  = (long long)TT * DD;
    const long long ATTN_E = (long long)HH * TT * TT;

    float* attn;
    if ((long long)out_size >= OUT_E + ATTN_E) {
        attn = outp + OUT_E;
    } else {
        void* p = 0;
        cudaGetSymbolAddress(&p, g_attn_scratch);
        attn = (float*)p;
    }

    const int SCORES_SMEM = 73728;
    cudaFuncSetAttribute(scores_kernel, cudaFuncAttributeMaxDynamicSharedMemorySize, SCORES_SMEM);

    gemm_kernel<0><<<dim3(DD / 64, TT / 128, 3), 256>>>(x, Wq, Wk, Wv, nullptr);
    scores_kernel <<<dim3(TT / 128, TT / 128, HH), 256, SCORES_SMEM>>>(attn);
    softmax_kernel<<<dim3(TT, HH), 256>>>(attn);
    av_kernel     <<<dim3(TT / 128, HH), 256>>>(attn);
    // MODE 1 reads g_OH via device-side symbol (host passes nullptr!)
    gemm_kernel<1><<<dim3(DD / 64, TT / 128, 1), 256>>>(nullptr, Wo, nullptr, nullptr, outp);
}